// round 13
// baseline (speedup 1.0000x reference)
#include <cuda_runtime.h>
#include <cuda_fp16.h>
#include <mma.h>
#include <cstdint>

using namespace nvcuda;

// Problem constants (fixed shapes)
#define N_NODES  50000
#define N_EDGES  1600000
#define N_GRAPHS 64
#define D_IN     128
#define D_H      512
#define D_OUT    16

// persistent mega-kernel geometry (must stay co-resident: 4 blocks/SM x 148 SMs)
#define NBLK   592
#define NTHR   256
#define NWARPS (NBLK * NTHR / 32)

// gemm smem strides (padded to break 128B bank-period alignment)
#define LDA  136   // halves (272B row stride)
#define LDBN 136   // halves (272B row stride), B tile is 128 cols + 8 pad
#define LDC  132   // floats (528B row stride)
// A[64][LDA] + B[128][LDBN] halves = 52224 B; C aliases this region (33792 B);
// bs[64] ints live after the half region.
#define GEMM_HALF_BYTES (64 * LDA * 2 + 128 * LDBN * 2)
#define GEMM_SMEM_BYTES (GEMM_HALF_BYTES + 64 * 4)

// ---------------- device scratch (no allocation allowed) ----------------
// Invariant: g_deg, g_cur, g_gsum, g_gcnt are ZERO at entry to kernel_launch
// (zero-init at module load; re-zeroed by k_tail at the end of every launch).
__device__ __half g_h[3][(size_t)N_NODES * D_IN];  // 3 x 12.8 MB
__device__ __half g_w1h[D_IN * D_H];               // 128 KB
__device__ int   g_deg[N_NODES];
__device__ float g_invdeg[N_NODES];
__device__ int   g_off[N_NODES + 1];
__device__ int   g_cur[N_NODES];
__device__ int   g_csr[N_EDGES];                   // 6.4 MB
__device__ float g_gsum[N_GRAPHS * D_H];
__device__ int   g_gcnt[N_GRAPHS];

// global barrier state (monotonic generation; never reset -> deterministic)
__device__ unsigned g_cnt_bar;
__device__ volatile unsigned g_gen_bar;

// ---------------- helpers ----------------
__device__ __forceinline__ void acc_u2(float2& a0, float2& a1, uint2 v) {
    float2 f0 = __half22float2(*(__half2*)&v.x);
    float2 f1 = __half22float2(*(__half2*)&v.y);
    a0.x += f0.x; a0.y += f0.y;
    a1.x += f1.x; a1.y += f1.y;
}

// all-block barrier; requires all NBLK blocks co-resident
__device__ __forceinline__ void gbar() {
    __syncthreads();
    if (threadIdx.x == 0) {
        unsigned gen = g_gen_bar;
        __threadfence();
        if (atomicAdd(&g_cnt_bar, 1u) == NBLK - 1) {
            g_cnt_bar = 0;
            __threadfence();
            g_gen_bar = gen + 1;
        } else {
            while (g_gen_bar == gen) { }
        }
        __threadfence();
    }
    __syncthreads();
}

// ---------------- kernels ----------------

// Launch 1: x->fp16, w1->fp16, degree count, per-graph node histogram.
__global__ void k_prep(const float2* __restrict__ x, const float2* __restrict__ w1,
                       const int* __restrict__ rows, const int* __restrict__ batch) {
    __shared__ int h[N_GRAPHS];
    if (threadIdx.x < N_GRAPHS) h[threadIdx.x] = 0;
    __syncthreads();
    const int stride = gridDim.x * blockDim.x;
    int gid = blockIdx.x * blockDim.x + threadIdx.x;
    for (int i = gid; i < N_NODES * (D_IN / 2); i += stride)
        ((__half2*)g_h[0])[i] = __float22half2_rn(__ldg(&x[i]));
    for (int i = gid; i < D_IN * D_H / 2; i += stride)
        ((__half2*)g_w1h)[i] = __float22half2_rn(__ldg(&w1[i]));
    for (int e = gid; e < N_EDGES; e += stride)
        atomicAdd(&g_deg[__ldg(&rows[e])], 1);
    for (int i = gid; i < N_NODES; i += stride)
        atomicAdd(&h[__ldg(&batch[i])], 1);
    __syncthreads();
    if (threadIdx.x < N_GRAPHS) atomicAdd(&g_gcnt[threadIdx.x], h[threadIdx.x]);
}

// Launch 2: single-block exclusive scan of deg -> off, plus invdeg
__global__ void __launch_bounds__(1024) k_scan() {
    const int C = (N_NODES + 1023) / 1024;  // 49
    int t = threadIdx.x;
    int start = t * C;
    int end = min(start + C, N_NODES);

    int sum = 0;
    for (int i = start; i < end; i++) sum += g_deg[i];

    __shared__ int part[1024];
    part[t] = sum;
    __syncthreads();
    for (int d = 1; d < 1024; d <<= 1) {
        int v = (t >= d) ? part[t - d] : 0;
        __syncthreads();
        part[t] += v;
        __syncthreads();
    }
    int run = (t == 0) ? 0 : part[t - 1];
    for (int i = start; i < end; i++) { g_off[i] = run; run += g_deg[i]; }
    if (end == N_NODES) g_off[N_NODES] = run;

    for (int i = t; i < N_NODES; i += 1024)
        g_invdeg[i] = 1.0f / (float)(g_deg[i] + 1);  // +1 self loop
}

// one propagation pass over all nodes, grid-strided warp-per-node
__device__ __forceinline__ void hop_pass(const uint2* __restrict__ src,
                                         uint2* __restrict__ dst,
                                         int gwarp, int lane) {
    for (int r = gwarp; r < N_NODES; r += NWARPS) {
        int js = __ldg(&g_off[r]);
        int je = __ldg(&g_off[r + 1]);

        uint2 u = src[(size_t)r * 32 + lane];   // self loop
        float2 a0 = __half22float2(*(__half2*)&u.x);
        float2 a1 = __half22float2(*(__half2*)&u.y);

        int j = js;
        for (; j + 16 <= je; j += 16) {
            int c[16];
            #pragma unroll
            for (int t = 0; t < 16; t++) c[t] = g_csr[j + t];
            uint2 v[16];
            #pragma unroll
            for (int t = 0; t < 16; t++) v[t] = src[(size_t)c[t] * 32 + lane];
            #pragma unroll
            for (int t = 0; t < 16; t++) acc_u2(a0, a1, v[t]);
        }
        for (; j + 4 <= je; j += 4) {
            int c[4];
            #pragma unroll
            for (int t = 0; t < 4; t++) c[t] = g_csr[j + t];
            uint2 v[4];
            #pragma unroll
            for (int t = 0; t < 4; t++) v[t] = src[(size_t)c[t] * 32 + lane];
            #pragma unroll
            for (int t = 0; t < 4; t++) acc_u2(a0, a1, v[t]);
        }
        for (; j < je; j++)
            acc_u2(a0, a1, src[(size_t)g_csr[j] * 32 + lane]);

        float s = __ldg(&g_invdeg[r]);
        a0.x *= s; a0.y *= s; a1.x *= s; a1.y *= s;

        __half2 lo = __float22half2_rn(a0);
        __half2 hi = __float22half2_rn(a1);
        uint2 out;
        out.x = *(unsigned*)&lo;
        out.y = *(unsigned*)&hi;
        dst[(size_t)r * 32 + lane] = out;
    }
}

// Launch 3 (persistent): CSR fill + 3 hops with global barriers.
__global__ void __launch_bounds__(NTHR, 4)
k_mega(const int* __restrict__ rows, const int* __restrict__ cols,
       __half* __restrict__ h0, __half* __restrict__ h1, __half* __restrict__ h2) {
    const int tid = blockIdx.x * NTHR + threadIdx.x;

    // phase 0: CSR fill (relies on g_cur == 0 at entry)
    for (int e = tid; e < N_EDGES; e += NBLK * NTHR) {
        int r = __ldg(&rows[e]);
        int p = atomicAdd(&g_cur[r], 1);
        g_csr[g_off[r] + p] = __ldg(&cols[e]);
    }
    gbar();

    const int gwarp = tid >> 5;
    const int lane  = tid & 31;
    hop_pass((const uint2*)h0, (uint2*)h1, gwarp, lane);
    gbar();
    hop_pass((const uint2*)h1, (uint2*)h2, gwarp, lane);
    gbar();
    hop_pass((const uint2*)h2, (uint2*)h0, gwarp, lane);
}

// Launch 4 (PROFILED SLOT): C = relu( A @ w1 + b1 ), fused per-graph pooling.
// Block tile: 64(M) x 128(N), K=128. 8 warps as 2(M)x4(N), warp tile 32x32.
// fp16 HMMA, fp32 accum. C staging aliases the A/B smem region (sync-separated).
__global__ void __launch_bounds__(256)
k_gemm_pool(const __half* __restrict__ A,
            const float* __restrict__ b1, const int* __restrict__ batch) {
    extern __shared__ char smc[];
    __half* As = (__half*)smc;                     // [64][LDA]
    __half* Bs = As + 64 * LDA;                    // [128][LDBN]
    float*  Cs = (float*)smc;                      // [64][LDC]  (aliases As/Bs)
    int*    bs = (int*)(smc + GEMM_HALF_BYTES);    // [64]

    const int row0 = blockIdx.x * 64;
    const int col0 = blockIdx.y * 128;
    const int tid  = threadIdx.x;

    // load A tile (uint4 = 8 halves), zero-pad beyond N_NODES
    for (int i = tid; i < 64 * 16; i += 256) {
        int r = i >> 4, q = i & 15;
        int node = row0 + r;
        uint4 v = make_uint4(0u, 0u, 0u, 0u);
        if (node < N_NODES)
            v = __ldg(((const uint4*)A) + (size_t)node * 16 + q);
        *(uint4*)(As + r * LDA + q * 8) = v;
    }
    // load B tile: w1h[128][512] cols [col0, col0+128)
    for (int i = tid; i < 128 * 16; i += 256) {
        int r = i >> 4, q = i & 15;
        uint4 v = __ldg((const uint4*)(g_w1h + (size_t)r * D_H + col0 + q * 8));
        *(uint4*)(Bs + r * LDBN + q * 8) = v;
    }
    if (tid < 64) {
        int node = row0 + tid;
        bs[tid] = (node < N_NODES) ? __ldg(&batch[node]) : -1;
    }
    __syncthreads();

    const int wid = tid >> 5;
    const int wm = (wid & 1) * 32;     // M offset
    const int wn = (wid >> 1) * 32;    // N offset
    wmma::fragment<wmma::accumulator, 16, 16, 16, float> c00, c01, c10, c11;
    wmma::fill_fragment(c00, 0.0f);
    wmma::fill_fragment(c01, 0.0f);
    wmma::fill_fragment(c10, 0.0f);
    wmma::fill_fragment(c11, 0.0f);

    #pragma unroll
    for (int k = 0; k < 128; k += 16) {
        wmma::fragment<wmma::matrix_a, 16, 16, 16, __half, wmma::row_major> a0, a1;
        wmma::load_matrix_sync(a0, As + (wm +  0) * LDA + k, LDA);
        wmma::load_matrix_sync(a1, As + (wm + 16) * LDA + k, LDA);
        wmma::fragment<wmma::matrix_b, 16, 16, 16, __half, wmma::row_major> b0, b1f;
        wmma::load_matrix_sync(b0,  Bs + k * LDBN + wn,      LDBN);
        wmma::load_matrix_sync(b1f, Bs + k * LDBN + wn + 16, LDBN);
        wmma::mma_sync(c00, a0, b0,  c00);
        wmma::mma_sync(c01, a0, b1f, c01);
        wmma::mma_sync(c10, a1, b0,  c10);
        wmma::mma_sync(c11, a1, b1f, c11);
    }
    __syncthreads();   // all reads of As/Bs complete before aliasing writes to Cs

    wmma::store_matrix_sync(Cs + (wm +  0) * LDC + wn,      c00, LDC, wmma::mem_row_major);
    wmma::store_matrix_sync(Cs + (wm +  0) * LDC + wn + 16, c01, LDC, wmma::mem_row_major);
    wmma::store_matrix_sync(Cs + (wm + 16) * LDC + wn,      c10, LDC, wmma::mem_row_major);
    wmma::store_matrix_sync(Cs + (wm + 16) * LDC + wn + 16, c11, LDC, wmma::mem_row_major);
    __syncthreads();

    // epilogue: bias + relu + run-length per-graph accumulation (batch sorted).
    // 256 threads = 128 cols x 2 row-strips of 32 rows.
    {
        const int col = tid & 127;
        const int q   = tid >> 7;          // strip 0/1
        const int gcol = col0 + col;
        const float bias = __ldg(&b1[gcol]);
        int curg = -1;
        float run = 0.0f;
        #pragma unroll 4
        for (int rr = 0; rr < 32; rr++) {
            int r = q * 32 + rr;
            if (row0 + r >= N_NODES) break;
            int g = bs[r];
            float val = fmaxf(Cs[r * LDC + col] + bias, 0.0f);
            if (g != curg) {
                if (curg >= 0) atomicAdd(&g_gsum[curg * D_H + gcol], run);
                curg = g;
                run = val;
            } else {
                run += val;
            }
        }
        if (curg >= 0) atomicAdd(&g_gsum[curg * D_H + gcol], run);
    }
}

// Launch 5: fused tail: fc2 + fc3 + counter reset.
__global__ void __launch_bounds__(512)
k_tail(const float* __restrict__ w2, const float* __restrict__ b2,
       const float* __restrict__ wc, const float* __restrict__ bc,
       float* __restrict__ out) {
    __shared__ float s[D_H];
    __shared__ float p2[D_H];
    const int g = blockIdx.x;
    const int j = threadIdx.x;

    float cnt = fmaxf((float)g_gcnt[g], 1.0f);
    s[j] = g_gsum[g * D_H + j] / cnt;
    g_gsum[g * D_H + j] = 0.0f;                 // reset for next call
    __syncthreads();

    float acc = __ldg(&b2[j]);
    #pragma unroll 8
    for (int k = 0; k < D_H; k++) acc += s[k] * __ldg(&w2[(size_t)k * D_H + j]);
    p2[j] = acc;
    __syncthreads();

    const int o = j >> 5, lane = j & 31;
    float a = 0.0f;
    #pragma unroll
    for (int k = lane; k < D_H; k += 32) a += p2[k] * __ldg(&wc[k * D_OUT + o]);
    #pragma unroll
    for (int d = 16; d; d >>= 1) a += __shfl_down_sync(0xffffffffu, a, d);
    if (lane == 0) out[g * D_OUT + o] = a + __ldg(&bc[o]);

    if (j == 0) g_gcnt[g] = 0;
    for (int i = g * 512 + j; i < N_NODES; i += N_GRAPHS * 512) {
        g_deg[i] = 0;
        g_cur[i] = 0;
    }
}

// ---------------- launch ----------------
extern "C" void kernel_launch(void* const* d_in, const int* in_sizes, int n_in,
                              void* d_out, int out_size) {
    const float* x     = (const float*)d_in[0];
    const int*   ei    = (const int*)d_in[1];   // [2, E]
    const int*   batch = (const int*)d_in[2];
    const float* w1    = (const float*)d_in[3];
    const float* b1    = (const float*)d_in[4];
    const float* w2    = (const float*)d_in[5];
    const float* b2    = (const float*)d_in[6];
    const float* wc    = (const float*)d_in[7];
    const float* bc    = (const float*)d_in[8];

    const int* rows = ei;
    const int* cols = ei + N_EDGES;

    __half *h0, *h1, *h2;
    cudaGetSymbolAddress((void**)&h0, g_h);
    h1 = h0 + (size_t)N_NODES * D_IN;
    h2 = h1 + (size_t)N_NODES * D_IN;

    cudaFuncSetAttribute(k_gemm_pool, cudaFuncAttributeMaxDynamicSharedMemorySize,
                         GEMM_SMEM_BYTES);

    // 1: convert + degree + histogram
    k_prep<<<2048, 256>>>((const float2*)x, (const float2*)w1, rows, batch);
    // 2: offsets + invdeg
    k_scan<<<1, 1024>>>();
    // 3: persistent fill + 3 hops (global barriers inside)
    k_mega<<<NBLK, NTHR>>>(rows, cols, h0, h1, h2);
    // 4: fused GEMM + pooling  <- profiled slot (64x128 tiles, 32x32 warp tiles)
    dim3 ggrid((N_NODES + 63) / 64, D_H / 128);
    k_gemm_pool<<<ggrid, 256, GEMM_SMEM_BYTES>>>(h0, b1, batch);
    // 5: fused fc2 + fc3 + reset
    k_tail<<<N_GRAPHS, 512>>>(w2, b2, wc, bc, (float*)d_out);
}

// round 14
// speedup vs baseline: 1.0391x; 1.0391x over previous
#include <cuda_runtime.h>
#include <cuda_fp16.h>
#include <mma.h>
#include <cstdint>

using namespace nvcuda;

// Problem constants (fixed shapes)
#define N_NODES  50000
#define N_EDGES  1600000
#define N_GRAPHS 64
#define D_IN     128
#define D_H      512
#define D_OUT    16

// persistent mega-kernel geometry (must stay co-resident: 4 blocks/SM x 148 SMs)
#define NBLK   592
#define NTHR   256
#define NWARPS (NBLK * NTHR / 32)

// gemm smem strides (padded to break 128B bank-period alignment)
#define LDA  136   // halves (272B row stride)
#define LDBN 136   // halves (272B row stride), B tile is 128 cols + 8 pad
#define LDC  132   // floats (528B row stride)
// A[64][LDA] + B[128][LDBN] halves = 52224 B; C aliases this region (33792 B);
// bs[64] ints live after the half region.
#define GEMM_HALF_BYTES (64 * LDA * 2 + 128 * LDBN * 2)
#define GEMM_SMEM_BYTES (GEMM_HALF_BYTES + 64 * 4)

// ---------------- device scratch (no allocation allowed) ----------------
// Invariant: g_deg, g_cur, g_gsum, g_gcnt are ZERO at entry to kernel_launch
// (zero-init at module load; re-zeroed by k_tail at the end of every launch).
__device__ __half g_h[3][(size_t)N_NODES * D_IN];  // 3 x 12.8 MB
__device__ __half g_w1h[D_IN * D_H];               // 128 KB
__device__ int   g_deg[N_NODES];
__device__ float g_invdeg[N_NODES];
__device__ int   g_off[N_NODES + 1];
__device__ int   g_cur[N_NODES];
__device__ int   g_csr[N_EDGES];                   // 6.4 MB
__device__ float g_gsum[N_GRAPHS * D_H];
__device__ int   g_gcnt[N_GRAPHS];

// global barrier state (monotonic generation; never reset -> deterministic)
__device__ unsigned g_cnt_bar;
__device__ volatile unsigned g_gen_bar;

// ---------------- helpers ----------------
__device__ __forceinline__ void acc_u2(float2& a0, float2& a1, uint2 v) {
    float2 f0 = __half22float2(*(__half2*)&v.x);
    float2 f1 = __half22float2(*(__half2*)&v.y);
    a0.x += f0.x; a0.y += f0.y;
    a1.x += f1.x; a1.y += f1.y;
}

// all-block barrier; requires all NBLK blocks co-resident
__device__ __forceinline__ void gbar() {
    __syncthreads();
    if (threadIdx.x == 0) {
        unsigned gen = g_gen_bar;
        __threadfence();
        if (atomicAdd(&g_cnt_bar, 1u) == NBLK - 1) {
            g_cnt_bar = 0;
            __threadfence();
            g_gen_bar = gen + 1;
        } else {
            while (g_gen_bar == gen) { }
        }
        __threadfence();
    }
    __syncthreads();
}

// ---------------- kernels ----------------

// Launch 1: x->fp16, w1->fp16, degree count, per-graph node histogram.
__global__ void k_prep(const float2* __restrict__ x, const float2* __restrict__ w1,
                       const int* __restrict__ rows, const int* __restrict__ batch) {
    __shared__ int h[N_GRAPHS];
    if (threadIdx.x < N_GRAPHS) h[threadIdx.x] = 0;
    __syncthreads();
    const int stride = gridDim.x * blockDim.x;
    int gid = blockIdx.x * blockDim.x + threadIdx.x;
    for (int i = gid; i < N_NODES * (D_IN / 2); i += stride)
        ((__half2*)g_h[0])[i] = __float22half2_rn(__ldg(&x[i]));
    for (int i = gid; i < D_IN * D_H / 2; i += stride)
        ((__half2*)g_w1h)[i] = __float22half2_rn(__ldg(&w1[i]));
    for (int e = gid; e < N_EDGES; e += stride)
        atomicAdd(&g_deg[__ldg(&rows[e])], 1);
    for (int i = gid; i < N_NODES; i += stride)
        atomicAdd(&h[__ldg(&batch[i])], 1);
    __syncthreads();
    if (threadIdx.x < N_GRAPHS) atomicAdd(&g_gcnt[threadIdx.x], h[threadIdx.x]);
}

// Launch 2: single-block exclusive scan of deg -> off, plus invdeg
__global__ void __launch_bounds__(1024) k_scan() {
    const int C = (N_NODES + 1023) / 1024;  // 49
    int t = threadIdx.x;
    int start = t * C;
    int end = min(start + C, N_NODES);

    int sum = 0;
    for (int i = start; i < end; i++) sum += g_deg[i];

    __shared__ int part[1024];
    part[t] = sum;
    __syncthreads();
    for (int d = 1; d < 1024; d <<= 1) {
        int v = (t >= d) ? part[t - d] : 0;
        __syncthreads();
        part[t] += v;
        __syncthreads();
    }
    int run = (t == 0) ? 0 : part[t - 1];
    for (int i = start; i < end; i++) { g_off[i] = run; run += g_deg[i]; }
    if (end == N_NODES) g_off[N_NODES] = run;

    for (int i = t; i < N_NODES; i += 1024)
        g_invdeg[i] = 1.0f / (float)(g_deg[i] + 1);  // +1 self loop
}

// one propagation pass over all nodes, grid-strided warp-per-node
__device__ __forceinline__ void hop_pass(const uint2* __restrict__ src,
                                         uint2* __restrict__ dst,
                                         int gwarp, int lane) {
    for (int r = gwarp; r < N_NODES; r += NWARPS) {
        int js = __ldg(&g_off[r]);
        int je = __ldg(&g_off[r + 1]);

        uint2 u = src[(size_t)r * 32 + lane];   // self loop
        float2 a0 = __half22float2(*(__half2*)&u.x);
        float2 a1 = __half22float2(*(__half2*)&u.y);

        int j = js;
        for (; j + 16 <= je; j += 16) {
            int c[16];
            #pragma unroll
            for (int t = 0; t < 16; t++) c[t] = g_csr[j + t];
            uint2 v[16];
            #pragma unroll
            for (int t = 0; t < 16; t++) v[t] = src[(size_t)c[t] * 32 + lane];
            #pragma unroll
            for (int t = 0; t < 16; t++) acc_u2(a0, a1, v[t]);
        }
        for (; j + 4 <= je; j += 4) {
            int c[4];
            #pragma unroll
            for (int t = 0; t < 4; t++) c[t] = g_csr[j + t];
            uint2 v[4];
            #pragma unroll
            for (int t = 0; t < 4; t++) v[t] = src[(size_t)c[t] * 32 + lane];
            #pragma unroll
            for (int t = 0; t < 4; t++) acc_u2(a0, a1, v[t]);
        }
        for (; j < je; j++)
            acc_u2(a0, a1, src[(size_t)g_csr[j] * 32 + lane]);

        float s = __ldg(&g_invdeg[r]);
        a0.x *= s; a0.y *= s; a1.x *= s; a1.y *= s;

        __half2 lo = __float22half2_rn(a0);
        __half2 hi = __float22half2_rn(a1);
        uint2 out;
        out.x = *(unsigned*)&lo;
        out.y = *(unsigned*)&hi;
        dst[(size_t)r * 32 + lane] = out;
    }
}

// Launch 3 (persistent): CSR fill + 3 hops with global barriers.
__global__ void __launch_bounds__(NTHR, 4)
k_mega(const int* __restrict__ rows, const int* __restrict__ cols,
       __half* __restrict__ h0, __half* __restrict__ h1, __half* __restrict__ h2) {
    const int tid = blockIdx.x * NTHR + threadIdx.x;

    // phase 0: CSR fill (relies on g_cur == 0 at entry)
    for (int e = tid; e < N_EDGES; e += NBLK * NTHR) {
        int r = __ldg(&rows[e]);
        int p = atomicAdd(&g_cur[r], 1);
        g_csr[g_off[r] + p] = __ldg(&cols[e]);
    }
    gbar();

    const int gwarp = tid >> 5;
    const int lane  = tid & 31;
    hop_pass((const uint2*)h0, (uint2*)h1, gwarp, lane);
    gbar();
    hop_pass((const uint2*)h1, (uint2*)h2, gwarp, lane);
    gbar();
    hop_pass((const uint2*)h2, (uint2*)h0, gwarp, lane);
}

// Launch 4 (PROFILED SLOT): C = relu( A @ w1 + b1 ), fused per-graph pooling.
// Block tile: 64(M) x 128(N), K=128. 8 warps as 2(M)x4(N), warp tile 32x32.
// fp16 HMMA, fp32 accum. C staging aliases the A/B smem region (sync-separated).
__global__ void __launch_bounds__(256)
k_gemm_pool(const __half* __restrict__ A,
            const float* __restrict__ b1, const int* __restrict__ batch) {
    extern __shared__ char smc[];
    __half* As = (__half*)smc;                     // [64][LDA]
    __half* Bs = As + 64 * LDA;                    // [128][LDBN]
    float*  Cs = (float*)smc;                      // [64][LDC]  (aliases As/Bs)
    int*    bs = (int*)(smc + GEMM_HALF_BYTES);    // [64]

    const int row0 = blockIdx.x * 64;
    const int col0 = blockIdx.y * 128;
    const int tid  = threadIdx.x;

    // load A tile (uint4 = 8 halves), zero-pad beyond N_NODES
    for (int i = tid; i < 64 * 16; i += 256) {
        int r = i >> 4, q = i & 15;
        int node = row0 + r;
        uint4 v = make_uint4(0u, 0u, 0u, 0u);
        if (node < N_NODES)
            v = __ldg(((const uint4*)A) + (size_t)node * 16 + q);
        *(uint4*)(As + r * LDA + q * 8) = v;
    }
    // load B tile: w1h[128][512] cols [col0, col0+128)
    for (int i = tid; i < 128 * 16; i += 256) {
        int r = i >> 4, q = i & 15;
        uint4 v = __ldg((const uint4*)(g_w1h + (size_t)r * D_H + col0 + q * 8));
        *(uint4*)(Bs + r * LDBN + q * 8) = v;
    }
    if (tid < 64) {
        int node = row0 + tid;
        bs[tid] = (node < N_NODES) ? __ldg(&batch[node]) : -1;
    }
    __syncthreads();

    const int wid = tid >> 5;
    const int wm = (wid & 1) * 32;     // M offset
    const int wn = (wid >> 1) * 32;    // N offset
    wmma::fragment<wmma::accumulator, 16, 16, 16, float> c00, c01, c10, c11;
    wmma::fill_fragment(c00, 0.0f);
    wmma::fill_fragment(c01, 0.0f);
    wmma::fill_fragment(c10, 0.0f);
    wmma::fill_fragment(c11, 0.0f);

    #pragma unroll
    for (int k = 0; k < 128; k += 16) {
        wmma::fragment<wmma::matrix_a, 16, 16, 16, __half, wmma::row_major> a0, a1;
        wmma::load_matrix_sync(a0, As + (wm +  0) * LDA + k, LDA);
        wmma::load_matrix_sync(a1, As + (wm + 16) * LDA + k, LDA);
        wmma::fragment<wmma::matrix_b, 16, 16, 16, __half, wmma::row_major> b0, b1f;
        wmma::load_matrix_sync(b0,  Bs + k * LDBN + wn,      LDBN);
        wmma::load_matrix_sync(b1f, Bs + k * LDBN + wn + 16, LDBN);
        wmma::mma_sync(c00, a0, b0,  c00);
        wmma::mma_sync(c01, a0, b1f, c01);
        wmma::mma_sync(c10, a1, b0,  c10);
        wmma::mma_sync(c11, a1, b1f, c11);
    }
    __syncthreads();   // all reads of As/Bs complete before aliasing writes to Cs

    wmma::store_matrix_sync(Cs + (wm +  0) * LDC + wn,      c00, LDC, wmma::mem_row_major);
    wmma::store_matrix_sync(Cs + (wm +  0) * LDC + wn + 16, c01, LDC, wmma::mem_row_major);
    wmma::store_matrix_sync(Cs + (wm + 16) * LDC + wn,      c10, LDC, wmma::mem_row_major);
    wmma::store_matrix_sync(Cs + (wm + 16) * LDC + wn + 16, c11, LDC, wmma::mem_row_major);
    __syncthreads();

    // epilogue: bias + relu + run-length per-graph accumulation (batch sorted).
    // 256 threads = 128 cols x 2 row-strips of 32 rows.
    {
        const int col = tid & 127;
        const int q   = tid >> 7;          // strip 0/1
        const int gcol = col0 + col;
        const float bias = __ldg(&b1[gcol]);
        int curg = -1;
        float run = 0.0f;
        #pragma unroll 4
        for (int rr = 0; rr < 32; rr++) {
            int r = q * 32 + rr;
            if (row0 + r >= N_NODES) break;
            int g = bs[r];
            float val = fmaxf(Cs[r * LDC + col] + bias, 0.0f);
            if (g != curg) {
                if (curg >= 0) atomicAdd(&g_gsum[curg * D_H + gcol], run);
                curg = g;
                run = val;
            } else {
                run += val;
            }
        }
        if (curg >= 0) atomicAdd(&g_gsum[curg * D_H + gcol], run);
    }
}

// Launch 5: fused tail: fc2 + fc3 + counter reset.
__global__ void __launch_bounds__(512)
k_tail(const float* __restrict__ w2, const float* __restrict__ b2,
       const float* __restrict__ wc, const float* __restrict__ bc,
       float* __restrict__ out) {
    __shared__ float s[D_H];
    __shared__ float p2[D_H];
    const int g = blockIdx.x;
    const int j = threadIdx.x;

    float cnt = fmaxf((float)g_gcnt[g], 1.0f);
    s[j] = g_gsum[g * D_H + j] / cnt;
    g_gsum[g * D_H + j] = 0.0f;                 // reset for next call
    __syncthreads();

    float acc = __ldg(&b2[j]);
    #pragma unroll 8
    for (int k = 0; k < D_H; k++) acc += s[k] * __ldg(&w2[(size_t)k * D_H + j]);
    p2[j] = acc;
    __syncthreads();

    const int o = j >> 5, lane = j & 31;
    float a = 0.0f;
    #pragma unroll
    for (int k = lane; k < D_H; k += 32) a += p2[k] * __ldg(&wc[k * D_OUT + o]);
    #pragma unroll
    for (int d = 16; d; d >>= 1) a += __shfl_down_sync(0xffffffffu, a, d);
    if (lane == 0) out[g * D_OUT + o] = a + __ldg(&bc[o]);

    if (j == 0) g_gcnt[g] = 0;
    for (int i = g * 512 + j; i < N_NODES; i += N_GRAPHS * 512) {
        g_deg[i] = 0;
        g_cur[i] = 0;
    }
}

// ---------------- launch ----------------
extern "C" void kernel_launch(void* const* d_in, const int* in_sizes, int n_in,
                              void* d_out, int out_size) {
    const float* x     = (const float*)d_in[0];
    const int*   ei    = (const int*)d_in[1];   // [2, E]
    const int*   batch = (const int*)d_in[2];
    const float* w1    = (const float*)d_in[3];
    const float* b1    = (const float*)d_in[4];
    const float* w2    = (const float*)d_in[5];
    const float* b2    = (const float*)d_in[6];
    const float* wc    = (const float*)d_in[7];
    const float* bc    = (const float*)d_in[8];

    const int* rows = ei;
    const int* cols = ei + N_EDGES;

    __half *h0, *h1, *h2;
    cudaGetSymbolAddress((void**)&h0, g_h);
    h1 = h0 + (size_t)N_NODES * D_IN;
    h2 = h1 + (size_t)N_NODES * D_IN;

    cudaFuncSetAttribute(k_gemm_pool, cudaFuncAttributeMaxDynamicSharedMemorySize,
                         GEMM_SMEM_BYTES);

    // 1: convert + degree + histogram
    k_prep<<<2048, 256>>>((const float2*)x, (const float2*)w1, rows, batch);
    // 2: offsets + invdeg
    k_scan<<<1, 1024>>>();
    // 3: persistent fill + 3 hops (global barriers inside)
    k_mega<<<NBLK, NTHR>>>(rows, cols, h0, h1, h2);
    // 4: fused GEMM + pooling  <- profiled slot (64x128 tiles, 32x32 warp tiles)
    dim3 ggrid((N_NODES + 63) / 64, D_H / 128);
    k_gemm_pool<<<ggrid, 256, GEMM_SMEM_BYTES>>>(h0, b1, batch);
    // 5: fused fc2 + fc3 + reset
    k_tail<<<N_GRAPHS, 512>>>(w2, b2, wc, bc, (float*)d_out);
}